// round 12
// baseline (speedup 1.0000x reference)
#include <cuda_runtime.h>
#include <cstdint>

#define T_MAX 512
#define B_SZ  64
#define IND   300
#define DIM   1024
#define TD    (T_MAX * DIM)
#define NCTA  128
#define GRP_CTAS 32
#define NGRP  4
#define PST   33

__device__ unsigned g_bar[NGRP * T_MAX];
__device__ int      g_len[B_SZ];

union F2U { float2 f; unsigned long long u; };

__device__ __forceinline__ unsigned long long fma2(unsigned long long a,
                                                   unsigned long long b,
                                                   unsigned long long c) {
    unsigned long long d;
    asm("fma.rn.f32x2 %0, %1, %2, %3;" : "=l"(d) : "l"(a), "l"(b), "l"(c));
    return d;
}
__device__ __forceinline__ unsigned long long add2(unsigned long long a,
                                                   unsigned long long b) {
    unsigned long long d;
    asm("add.rn.f32x2 %0, %1, %2;" : "=l"(d) : "l"(a), "l"(b));
    return d;
}

// ---------------------------------------------------------------------------
__global__ void zero_kernel() {
    int i = blockIdx.x * blockDim.x + threadIdx.x;
    if (i < NGRP * T_MAX) g_bar[i] = 0u;
    if (i < B_SZ)         g_len[i] = 0;
}

// ---------------------------------------------------------------------------
__global__ void __launch_bounds__(256) prep_kernel(const float* __restrict__ emb) {
    int b  = blockIdx.x & 63;
    int tq = blockIdx.x >> 6;
    int row = threadIdx.x >> 2;
    int l4  = threadIdx.x & 3;
    int t = tq * 64 + row;
    const float* p = emb + ((size_t)t * B_SZ + b) * IND;
    float s = 0.f;
    for (int i = l4; i < IND; i += 4) s += p[i];
    s += __shfl_xor_sync(~0u, s, 1);
    s += __shfl_xor_sync(~0u, s, 2);
    unsigned ball = __ballot_sync(~0u, (l4 == 0) && (s != 0.f));
    if ((threadIdx.x & 31) == 0) atomicAdd(&g_len[b], __popc(ball));
}

// ---------------------------------------------------------------------------
__global__ void tail_kernel(float* __restrict__ out, int out_size) {
    int b = threadIdx.x;
    long long tail = (long long)T_MAX * B_SZ * DIM;
    if (b < B_SZ && (long long)out_size >= tail + B_SZ)
        out[tail + b] = (float)g_len[b];
}

// ---------------------------------------------------------------------------
// ugemm (R11 tile): 64m x 128n, micro 8m x 4n.
// ---------------------------------------------------------------------------
#define KT 32
__global__ void __launch_bounds__(256) ugemm_kernel(const float* __restrict__ emb,
                                                    const float* __restrict__ win,
                                                    const float* __restrict__ bias,
                                                    float* __restrict__ out) {
    __shared__ float As[KT][68];
    __shared__ float Bs[KT][136];

    const int t  = blockIdx.x;
    const int n0 = blockIdx.y * 128;
    const int tid = threadIdx.x;
    const int tx = tid & 31, ty = tid >> 5;
    const float* arow = emb + (size_t)t * B_SZ * IND;

    float acc[8][4];
    #pragma unroll
    for (int i = 0; i < 8; i++)
        #pragma unroll
        for (int j = 0; j < 4; j++) acc[i][j] = 0.f;

    for (int kk = 0; kk < IND; kk += KT) {
        #pragma unroll
        for (int s = 0; s < 2; s++) {
            int idx = tid + s * 256;
            int row = idx >> 3;
            int f4  = idx & 7;
            int k   = kk + f4 * 4;
            float4 va = make_float4(0.f, 0.f, 0.f, 0.f);
            if (k < IND) va = *(const float4*)(arow + (size_t)row * IND + k);
            As[f4 * 4 + 0][row] = va.x; As[f4 * 4 + 1][row] = va.y;
            As[f4 * 4 + 2][row] = va.z; As[f4 * 4 + 3][row] = va.w;
        }
        #pragma unroll
        for (int s = 0; s < 4; s++) {
            int idx = tid + s * 256;
            int row = idx >> 3;
            int f4  = idx & 7;
            int k   = kk + f4 * 4;
            float4 vb = make_float4(0.f, 0.f, 0.f, 0.f);
            if (k < IND) vb = *(const float4*)(win + (size_t)(n0 + row) * IND + k);
            Bs[f4 * 4 + 0][row] = vb.x; Bs[f4 * 4 + 1][row] = vb.y;
            Bs[f4 * 4 + 2][row] = vb.z; Bs[f4 * 4 + 3][row] = vb.w;
        }
        __syncthreads();

        #pragma unroll
        for (int k = 0; k < KT; k++) {
            float4 a0 = *(const float4*)&As[k][ty * 8];
            float4 a1 = *(const float4*)&As[k][ty * 8 + 4];
            float4 bv = *(const float4*)&Bs[k][tx * 4];
            float av[8] = {a0.x, a0.y, a0.z, a0.w, a1.x, a1.y, a1.z, a1.w};
            float bb[4] = {bv.x, bv.y, bv.z, bv.w};
            #pragma unroll
            for (int i = 0; i < 8; i++)
                #pragma unroll
                for (int j = 0; j < 4; j++)
                    acc[i][j] = fmaf(av[i], bb[j], acc[i][j]);
        }
        __syncthreads();
    }

    const int n = n0 + tx * 4;
    float4 bv = *(const float4*)(bias + n);
    #pragma unroll
    for (int i = 0; i < 8; i++) {
        int b = ty * 8 + i;
        float4 v;
        v.x = acc[i][0] + bv.x; v.y = acc[i][1] + bv.y;
        v.z = acc[i][2] + bv.z; v.w = acc[i][3] + bv.w;
        *(float4*)(out + (size_t)b * TD + (size_t)t * DIM + n) = v;
    }
}

// ---------------------------------------------------------------------------
// rec_kernel: 128 CTAs = 4 groups(16 rows) x 32 d-CTAs(32 dims).
//   512 threads = 32 ks x 16 td; thread (ks,td): 2 dims (d0+2td..+1) over
//   k in [32ks,32ks+32) for all 16 rows. W: 32 ull regs.
//   Warp w owns compute cols [64w,64w+64) and stages exactly those: lane
//   handles quad 16w+(lane&15); rows 4c+2h, 4c+2h+1 in commit group c
//   (h = lane>>4) -> every thread has 2 cp.asyncs in EVERY group, so
//   per-thread wait_group + __syncwarp covers each 4-row chunk.
//   Reduction: 1 output per thread. Epilogue: 1 float, register leak carry.
// ---------------------------------------------------------------------------
__global__ void __launch_bounds__(512, 1) rec_kernel(const float* __restrict__ lw,
                                                     const float* __restrict__ init,
                                                     float* __restrict__ out) {
    extern __shared__ float sm[];
    float* xs = sm;                 // 16 * 1024 floats (swizzled)
    float* ps = sm + 16 * 1024;     // partials: 512 outputs * PST

    const int cta  = blockIdx.x;
    const int grp  = cta >> 5;
    const int lcta = cta & 31;
    const int b0   = grp * 16;
    const int d0   = lcta * 32;
    const int tid  = threadIdx.x;
    const int ks   = tid >> 4;          // 0..31
    const int td   = tid & 15;          // 0..15
    const int w    = tid >> 5;          // warp 0..15
    const int lane = tid & 31;
    const int h    = lane >> 4;         // lane half
    const int kb   = ks * 32;

    // ---- W: 2 dims x 32 k as f32x2 pairs (32 ull regs) ----
    unsigned long long w0p[16], w1p[16];
    {
        const float* r0 = lw + (size_t)(d0 + 2 * td) * DIM + kb;
        const float* r1 = r0 + DIM;
        #pragma unroll
        for (int q = 0; q < 8; q++) {
            float4 a = *(const float4*)(r0 + 4 * q);
            float4 b = *(const float4*)(r1 + 4 * q);
            F2U t0, t1, t2, t3;
            t0.f = make_float2(a.x, a.y); t1.f = make_float2(a.z, a.w);
            t2.f = make_float2(b.x, b.y); t3.f = make_float2(b.z, b.w);
            w0p[2 * q] = t0.u; w0p[2 * q + 1] = t1.u;
            w1p[2 * q] = t2.u; w1p[2 * q + 1] = t3.u;
        }
    }

    int off[8];
    #pragma unroll
    for (int q = 0; q < 8; q++) off[q] = (((q + ks) & 7) << 2);

    // staging: quad = 16w + (lane&15); swizzled dst offset
    const int quad    = 16 * w + (lane & 15);
    const int sl      = quad >> 3;
    const int pos     = quad & 7;
    const int st_off  = sl * 32 + (((pos + sl) & 7) << 2);
    const unsigned xs_u32 = (unsigned)__cvta_generic_to_shared(xs) + (unsigned)(st_off * 4);

    // reduced output: out index == tid -> (row, dloc)
    const int r_row = tid >> 5;         // 0..15
    const int r_d   = tid & 31;         // 0..31
    const int len   = g_len[b0 + r_row];
    float* optr = out + (size_t)(b0 + r_row) * TD + (d0 + r_d);
    unsigned* ctr_base = &g_bar[grp * T_MAX];

    float xo = init[d0 + r_d];
    float uv = __ldcg(optr);

    for (int t = 0; t < T_MAX; t++) {
        // ---- stage x_{t-1}: this lane's quad, 2 rows per commit group ----
        if (t == 0) {
            float4 v = *(const float4*)(init + quad * 4);
            #pragma unroll
            for (int r2 = 0; r2 < 8; r2++) {
                int row = 2 * ((r2 >> 1) * 2 + h) + (r2 & 1);   // any cover of 8 rows
                // simpler: rows h*8 + r2 would also cover; use chunk-aligned:
            }
            // plain: stage rows (4c + 2h + j)
            #pragma unroll
            for (int c = 0; c < 4; c++)
                #pragma unroll
                for (int j = 0; j < 2; j++) {
                    int row = 4 * c + 2 * h + j;
                    *(float4*)(xs + row * 1024 + st_off) = v;
                }
            __syncwarp();
        } else {
            const float* src = out + (size_t)b0 * TD + (size_t)(t - 1) * DIM + quad * 4;
            #pragma unroll
            for (int c = 0; c < 4; c++) {
                #pragma unroll
                for (int j = 0; j < 2; j++) {
                    int row = 4 * c + 2 * h + j;
                    asm volatile("cp.async.cg.shared.global [%0], [%1], 16;"
                                 :: "r"(xs_u32 + (unsigned)(row * 4096)),
                                    "l"(src + (size_t)row * TD) : "memory");
                }
                asm volatile("cp.async.commit_group;" ::: "memory");
            }
        }

        // ---- compute partials: 4 chunks of 4 rows, warp-scope waits ----
        #pragma unroll
        for (int c = 0; c < 4; c++) {
            if (t != 0) {
                if      (c == 0) asm volatile("cp.async.wait_group 3;" ::: "memory");
                else if (c == 1) asm volatile("cp.async.wait_group 2;" ::: "memory");
                else if (c == 2) asm volatile("cp.async.wait_group 1;" ::: "memory");
                else             asm volatile("cp.async.wait_group 0;" ::: "memory");
                __syncwarp();
            }
            #pragma unroll
            for (int rr = 0; rr < 4; rr++) {
                int b = c * 4 + rr;
                const float* xr = xs + b * 1024 + kb;
                unsigned long long a0a = 0ull, a0b = 0ull, a1a = 0ull, a1b = 0ull;
                #pragma unroll
                for (int q = 0; q < 8; q++) {
                    ulonglong2 v = *(const ulonglong2*)(xr + off[q]);
                    a0a = fma2(v.x, w0p[2 * q],     a0a);
                    a0b = fma2(v.y, w0p[2 * q + 1], a0b);
                    a1a = fma2(v.x, w1p[2 * q],     a1a);
                    a1b = fma2(v.y, w1p[2 * q + 1], a1b);
                }
                F2U s0, s1;
                s0.u = add2(a0a, a0b);
                s1.u = add2(a1a, a1b);
                float* pb = ps + (size_t)(b * 32 + 2 * td) * PST + ks;
                pb[0]   = s0.f.x + s0.f.y;
                pb[PST] = s1.f.x + s1.f.y;
            }
        }
        __syncthreads();

        // ---- reduction: one output per thread (conflict-free banks) ----
        float sum = 0.f;
        {
            const float* p = ps + (size_t)tid * PST;
            #pragma unroll
            for (int i = 0; i < 32; i++) sum += p[i];
        }

        // ---- epilogue ----
        {
            float m = (t < len) ? 1.f : 0.f;
            float y = (0.5f * tanhf(uv + sum) + 0.5f * xo) * m;
            optr[(size_t)t * DIM] = y;
            xo = y;
        }
        {
            int tn = (t + 1 < T_MAX) ? t + 1 : t;
            uv = __ldcg(optr + (size_t)tn * DIM);
        }

        // ---- per-group grid barrier (32 CTAs) ----
        __syncthreads();
        if (tid == 0) {
            unsigned* ctr = ctr_base + t;
            asm volatile("red.release.gpu.global.add.u32 [%0], 1;" :: "l"(ctr) : "memory");
            unsigned v;
            do {
                asm volatile("ld.relaxed.gpu.global.u32 %0, [%1];" : "=r"(v) : "l"(ctr) : "memory");
            } while (v < GRP_CTAS);
            asm volatile("ld.acquire.gpu.global.u32 %0, [%1];" : "=r"(v) : "l"(ctr) : "memory");
        }
        __syncthreads();
    }
}

// ---------------------------------------------------------------------------
extern "C" void kernel_launch(void* const* d_in, const int* in_sizes, int n_in,
                              void* d_out, int out_size) {
    const float* emb  = (const float*)d_in[0];
    const float* win  = (const float*)d_in[1];
    const float* lw   = (const float*)d_in[2];
    const float* bias = (const float*)d_in[3];
    const float* init = (const float*)d_in[4];
    float* out = (float*)d_out;

    zero_kernel<<<8, 256>>>();
    prep_kernel<<<512, 256>>>(emb);

    dim3 g(T_MAX, DIM / 128);
    ugemm_kernel<<<g, 256>>>(emb, win, bias, out);

    int smem = (16 * 1024 + 512 * PST) * (int)sizeof(float);   // ~130 KB
    cudaFuncSetAttribute(rec_kernel, cudaFuncAttributeMaxDynamicSharedMemorySize, smem);
    rec_kernel<<<NCTA, 512, smem>>>(lw, init, out);

    tail_kernel<<<1, 64>>>(out, out_size);
}